// round 6
// baseline (speedup 1.0000x reference)
#include <cuda_runtime.h>

#define NN 100000
#define DD 256
#define EE 300000
#define NB 98   // ceil(NN/1024)

typedef unsigned long long ull;

// ---------------- scratch ----------------
__device__ __align__(16) float g_acc[NN * DD];
__device__ __align__(16) float g_x1[NN * DD];
__device__ __align__(16) float g_x2[NN * DD];
__device__ int   g_degi[NN];
__device__ float g_invdeg[NN];
__device__ int   g_off[NN];
__device__ int   g_cursor[NN];
__device__ int   g_csr[EE];
__device__ int   g_src[EE];
__device__ int   g_dst[EE];
__device__ int   g_is64;
__device__ int   g_bsum[NB];
__device__ int   g_bsumex[NB];
__device__ float g_sagg[NN];            // invdeg * max|agg row|
__device__ float g_mx0[NN];             // max|x0 row|
__device__ float g_mxA[NN];             // max x1 row (relu >= 0)
__device__ float g_mxB[NN];             // max x2 row
__device__ float g_tm[256];             // per-W-row scale / 127
__device__ __align__(16) signed char g_B1[256 * 512];  // W slice 1, [m][k]
__device__ __align__(16) signed char g_B2[256 * 512];  // W slice 2

// ---------------- index dtype detection + conversion ----------------
__global__ void detect_kernel(const unsigned int* __restrict__ w) {
    if (threadIdx.x == 0 && blockIdx.x == 0) {
        unsigned int s = 0;
        #pragma unroll 1
        for (int i = 1; i < 256; i += 2) s |= w[i];
        g_is64 = (s == 0u) ? 1 : 0;
    }
}

__global__ void convert_kernel(const void* __restrict__ edge) {
    int e = blockIdx.x * blockDim.x + threadIdx.x;
    if (e >= EE) return;
    if (g_is64) {
        const long long* p = (const long long*)edge;
        g_src[e] = (int)p[e];
        g_dst[e] = (int)p[EE + e];
    } else {
        const int* p = (const int*)edge;
        g_src[e] = p[e];
        g_dst[e] = p[EE + e];
    }
}

// ---------------- degree + CSR build ----------------
__global__ void zero_deg_kernel() {
    int n = blockIdx.x * blockDim.x + threadIdx.x;
    if (n < NN) g_degi[n] = 0;
}
__global__ void deg_kernel() {
    int e = blockIdx.x * blockDim.x + threadIdx.x;
    if (e < EE) atomicAdd(&g_degi[g_dst[e]], 1);
}
__global__ void invdeg_kernel() {
    int n = blockIdx.x * blockDim.x + threadIdx.x;
    if (n < NN) g_invdeg[n] = 1.0f / fmaxf((float)g_degi[n], 1.0f);
}

__global__ void scanA_kernel() {
    __shared__ int sh[1024];
    int t = threadIdx.x;
    int n = blockIdx.x * 1024 + t;
    int v = (n < NN) ? g_degi[n] : 0;
    sh[t] = v;
    __syncthreads();
    #pragma unroll
    for (int off = 512; off > 0; off >>= 1) {
        if (t < off) sh[t] += sh[t + off];
        __syncthreads();
    }
    if (t == 0) g_bsum[blockIdx.x] = sh[0];
}

__global__ void scanB_kernel() {
    if (threadIdx.x == 0 && blockIdx.x == 0) {
        int acc = 0;
        for (int i = 0; i < NB; i++) {
            g_bsumex[i] = acc;
            acc += g_bsum[i];
        }
    }
}

__global__ void scanC_kernel() {
    __shared__ int sh[1024];
    int t = threadIdx.x;
    int n = blockIdx.x * 1024 + t;
    int v = (n < NN) ? g_degi[n] : 0;
    sh[t] = v;
    __syncthreads();
    #pragma unroll
    for (int off = 1; off < 1024; off <<= 1) {
        int x = (t >= off) ? sh[t - off] : 0;
        __syncthreads();
        sh[t] += x;
        __syncthreads();
    }
    if (n < NN) {
        int ex = g_bsumex[blockIdx.x] + sh[t] - v;
        g_off[n] = ex;
        g_cursor[n] = ex;
    }
}

__global__ void fill_kernel() {
    int e = blockIdx.x * blockDim.x + threadIdx.x;
    if (e >= EE) return;
    int pos = atomicAdd(&g_cursor[g_dst[e]], 1);
    g_csr[pos] = g_src[e];
}

// ---------------- per-row max|x0| ----------------
__global__ __launch_bounds__(256) void maxabs0_kernel(const float* __restrict__ x0) {
    int warp = (blockIdx.x * blockDim.x + threadIdx.x) >> 5;
    if (warp >= NN) return;
    int lane = threadIdx.x & 31;
    const float4* r = (const float4*)(x0 + (size_t)warp * DD);
    float4 v0 = r[lane];
    float4 v1 = r[lane + 32];
    float m = fmaxf(fmaxf(fmaxf(fabsf(v0.x), fabsf(v0.y)), fmaxf(fabsf(v0.z), fabsf(v0.w))),
                    fmaxf(fmaxf(fabsf(v1.x), fabsf(v1.y)), fmaxf(fabsf(v1.z), fabsf(v1.w))));
    #pragma unroll
    for (int o = 16; o > 0; o >>= 1) m = fmaxf(m, __shfl_xor_sync(0xffffffffu, m, o));
    if (lane == 0) g_mx0[warp] = m;
}

__global__ void zero_mx_kernel(int sel) {
    int n = blockIdx.x * blockDim.x + threadIdx.x;
    if (n < NN) ((sel == 1) ? g_mxA : g_mxB)[n] = 0.f;
}

// ---------------- aggregation: warp per node, CSR gather-sum + row scale ----------------
__global__ __launch_bounds__(256) void aggregate_kernel(const float* __restrict__ xext, int xsel) {
    const float* xin = (xsel == 0) ? xext : ((xsel == 1) ? g_x1 : g_x2);
    int warp = (blockIdx.x * blockDim.x + threadIdx.x) >> 5;
    if (warp >= NN) return;
    int lane = threadIdx.x & 31;
    int start = g_off[warp];
    int cnt = g_degi[warp];
    float4 a0 = make_float4(0.f, 0.f, 0.f, 0.f);
    float4 a1 = a0;
    #pragma unroll 1
    for (int i = 0; i < cnt; i++) {
        int s = g_csr[start + i];
        const float4* r = (const float4*)(xin + (size_t)s * DD);
        float4 v0 = r[lane];
        float4 v1 = r[lane + 32];
        a0.x += v0.x; a0.y += v0.y; a0.z += v0.z; a0.w += v0.w;
        a1.x += v1.x; a1.y += v1.y; a1.z += v1.z; a1.w += v1.w;
    }
    float4* o = (float4*)(g_acc + (size_t)warp * DD);
    o[lane] = a0;
    o[lane + 32] = a1;
    float m = fmaxf(fmaxf(fmaxf(fabsf(a0.x), fabsf(a0.y)), fmaxf(fabsf(a0.z), fabsf(a0.w))),
                    fmaxf(fmaxf(fabsf(a1.x), fabsf(a1.y)), fmaxf(fabsf(a1.z), fabsf(a1.w))));
    #pragma unroll
    for (int o2 = 16; o2 > 0; o2 >>= 1) m = fmaxf(m, __shfl_xor_sync(0xffffffffu, m, o2));
    if (lane == 0) g_sagg[warp] = m * g_invdeg[warp];
}

// ---------------- weight quantization: warp per m-row ----------------
__device__ __forceinline__ int q8(float x) {
    int v = __float2int_rn(x);
    return v > 127 ? 127 : (v < -127 ? -127 : v);
}
__device__ __forceinline__ unsigned pk4(int a, int b, int c, int d) {
    return (unsigned)(a & 255) | ((unsigned)(b & 255) << 8) |
           ((unsigned)(c & 255) << 16) | ((unsigned)(d & 255) << 24);
}

__global__ __launch_bounds__(256) void quantB_kernel(const float* __restrict__ Wl,
                                                     const float* __restrict__ Wr) {
    int m = blockIdx.x * 8 + (threadIdx.x >> 5);   // warp per W-row
    if (m >= 256) return;
    int lane = threadIdx.x & 31;
    float w[16];
    #pragma unroll
    for (int i = 0; i < 16; i++) {
        int k = lane * 16 + i;
        w[i] = (k < 256) ? Wl[m * 256 + k] : Wr[m * 256 + (k - 256)];
    }
    float t = 0.f;
    #pragma unroll
    for (int i = 0; i < 16; i++) t = fmaxf(t, fabsf(w[i]));
    #pragma unroll
    for (int o = 16; o > 0; o >>= 1) t = fmaxf(t, __shfl_xor_sync(0xffffffffu, t, o));
    t = fmaxf(t, 1e-30f);
    float qsc = 127.0f / t;
    int b1[16], b2[16];
    #pragma unroll
    for (int i = 0; i < 16; i++) {
        float v = w[i] * qsc;
        b1[i] = q8(v);
        b2[i] = q8((v - (float)b1[i]) * 256.0f);
    }
    uint4 p1, p2;
    p1.x = pk4(b1[0], b1[1], b1[2], b1[3]);   p1.y = pk4(b1[4], b1[5], b1[6], b1[7]);
    p1.z = pk4(b1[8], b1[9], b1[10], b1[11]); p1.w = pk4(b1[12], b1[13], b1[14], b1[15]);
    p2.x = pk4(b2[0], b2[1], b2[2], b2[3]);   p2.y = pk4(b2[4], b2[5], b2[6], b2[7]);
    p2.z = pk4(b2[8], b2[9], b2[10], b2[11]); p2.w = pk4(b2[12], b2[13], b2[14], b2[15]);
    *(uint4*)(g_B1 + m * 512 + lane * 16) = p1;
    *(uint4*)(g_B2 + m * 512 + lane * 16) = p2;
    if (lane == 0) g_tm[m] = t * (1.0f / 127.0f);
}

// ---------------- asm helpers ----------------
__device__ __forceinline__ unsigned sm_u32(const void* p) {
    unsigned r;
    asm("{ .reg .u64 t; cvta.to.shared.u64 t, %1; cvt.u32.u64 %0, t; }" : "=r"(r) : "l"(p));
    return r;
}
__device__ __forceinline__ void sts64(unsigned a, unsigned x, unsigned y) {
    asm volatile("st.shared.v2.b32 [%0], {%1,%2};" :: "r"(a), "r"(x), "r"(y));
}
__device__ __forceinline__ void cpasync16(unsigned smem, const void* g) {
    asm volatile("cp.async.cg.shared.global [%0], [%1], 16;" :: "r"(smem), "l"(g));
}
__device__ __forceinline__ void cpcommit() { asm volatile("cp.async.commit_group;"); }
__device__ __forceinline__ void cpwait0() { asm volatile("cp.async.wait_group 0;"); }
__device__ __forceinline__ void ldsm4(unsigned& r0, unsigned& r1, unsigned& r2, unsigned& r3, unsigned a) {
    asm volatile("ldmatrix.sync.aligned.m8n8.x4.shared.b16 {%0,%1,%2,%3}, [%4];"
                 : "=r"(r0), "=r"(r1), "=r"(r2), "=r"(r3) : "r"(a));
}
__device__ __forceinline__ void mma_s8(int* c, const unsigned* a, unsigned b0, unsigned b1) {
    asm volatile(
        "mma.sync.aligned.m16n8k32.row.col.s32.s8.s8.s32 "
        "{%0,%1,%2,%3}, {%4,%5,%6,%7}, {%8,%9}, {%0,%1,%2,%3};"
        : "+r"(c[0]), "+r"(c[1]), "+r"(c[2]), "+r"(c[3])
        : "r"(a[0]), "r"(a[1]), "r"(a[2]), "r"(a[3]), "r"(b0), "r"(b1));
}

// smem: rows 32B padded to 48B stride -> conflict-free ldsm
#define RSTR 48
#define SM_A1 0
#define SM_A2 3072             // 64 * 48
#define SM_B1 6144
#define SM_B2 (6144 + 12288)   // 256 * 48
#define SM_STG 30720
#define SM_TOT (2 * SM_STG)    // 61440

// ---------------- fused layer GEMM (int8 2-slice, s32 accum) ----------------
// out[r, m] = relu?( sum_k A[r,k] * W[m,k] + b[m] ), A = [invdeg*acc | xin] (K=512)
// CTA: 64 rows x 256 cols, 8 warps (2 wm x 4 wn), warp tile 32 x 64.
__global__ __launch_bounds__(256) void gemm_i8_kernel(
    const float* __restrict__ xext, int xsel,
    float* __restrict__ oext, int osel,
    const float* __restrict__ bias, int do_relu,
    int mxin_sel, int mxout_sel)
{
    extern __shared__ char smem[];
    const float* xin = (xsel == 0) ? xext : ((xsel == 1) ? g_x1 : g_x2);
    float* out = (osel == 0) ? oext : ((osel == 1) ? g_x1 : g_x2);
    const float* mxin = (mxin_sel == 0) ? g_mx0 : ((mxin_sel == 1) ? g_mxA : g_mxB);
    float* mxout = (mxout_sel == 1) ? g_mxA : g_mxB;

    const unsigned su = sm_u32(smem);
    const int tid = threadIdx.x;
    const int wid = tid >> 5;
    const int lane = tid & 31;
    const int wm = wid & 1;       // 2 warps over M (32 rows each)
    const int wn = wid >> 1;      // 4 warps over N (64 cols each)
    const int row0 = blockIdx.x * 64;

    // A quantize-loader geometry: thread -> row t>>2, k-octet t&3
    const int arow = tid >> 2;
    const int akq = tid & 3;
    const int gr = row0 + arow;
    const bool rok = gr < NN;
    const float invd = rok ? g_invdeg[gr] : 0.f;
    const float srow = rok ? fmaxf(fmaxf(g_sagg[gr], mxin[gr]), 1e-30f) : 1.f;
    const float* aggrow = g_acc + (size_t)(rok ? gr : 0) * DD;
    const float* xrow = xin + (size_t)(rok ? gr : 0) * DD;

    // B cp.async geometry: thread -> row t (0..255)
    const int brow = tid;

    // ldmatrix fragment addresses (stage-relative)
    const unsigned aoff = (unsigned)((wm * 32 + (lane & 15)) * RSTR + (lane >> 4) * 16);
    const unsigned boff = (unsigned)((wn * 64 + ((lane >> 4) & 1) * 8 + (lane & 7)) * RSTR
                                     + ((lane >> 3) & 1) * 16);

    int P1[2][8][4];
    int Pc[2][8][4];
    #pragma unroll
    for (int i = 0; i < 2; i++)
        #pragma unroll
        for (int j = 0; j < 8; j++)
            #pragma unroll
            for (int q = 0; q < 4; q++) { P1[i][j][q] = 0; Pc[i][j][q] = 0; }

    float4 pa0, pa1;
    float pqs;

    auto ldA = [&](int ck) {
        const int side = ck >> 3;
        const float* s = (side ? xrow : aggrow) + (ck & 7) * 32 + akq * 8;
        pqs = (side ? 1.f : invd) * (127.0f / srow);
        if (rok) {
            pa0 = *(const float4*)(s);
            pa1 = *(const float4*)(s + 4);
        } else {
            pa0 = make_float4(0.f, 0.f, 0.f, 0.f);
            pa1 = pa0;
        }
    };
    auto stsA = [&](int stg) {
        float v[8] = {pa0.x * pqs, pa0.y * pqs, pa0.z * pqs, pa0.w * pqs,
                      pa1.x * pqs, pa1.y * pqs, pa1.z * pqs, pa1.w * pqs};
        int q1[8], q2[8];
        #pragma unroll
        for (int i = 0; i < 8; i++) {
            q1[i] = q8(v[i]);
            q2[i] = q8((v[i] - (float)q1[i]) * 256.0f);
        }
        unsigned base = su + (unsigned)stg * SM_STG;
        unsigned off = (unsigned)(arow * RSTR + akq * 8);
        sts64(base + SM_A1 + off, pk4(q1[0], q1[1], q1[2], q1[3]), pk4(q1[4], q1[5], q1[6], q1[7]));
        sts64(base + SM_A2 + off, pk4(q2[0], q2[1], q2[2], q2[3]), pk4(q2[4], q2[5], q2[6], q2[7]));
    };
    auto cpB = [&](int ck, int stg) {
        unsigned base = su + (unsigned)stg * SM_STG;
        unsigned off = (unsigned)(brow * RSTR);
        size_t go = (size_t)brow * 512 + ck * 32;
        cpasync16(base + SM_B1 + off, g_B1 + go);
        cpasync16(base + SM_B1 + off + 16, g_B1 + go + 16);
        cpasync16(base + SM_B2 + off, g_B2 + go);
        cpasync16(base + SM_B2 + off + 16, g_B2 + go + 16);
        cpcommit();
    };

    ldA(0);
    stsA(0);
    cpB(0, 0);
    ldA(1);

    #pragma unroll 1
    for (int ck = 0; ck < 16; ck++) {
        const int s = ck & 1;
        cpwait0();
        __syncthreads();

        if (ck < 15) {
            stsA(s ^ 1);
            cpB(ck + 1, s ^ 1);
        }
        if (ck < 14) ldA(ck + 2);

        const unsigned sbase = su + (unsigned)s * SM_STG;

        // load A fragments (both slices, 2 mi tiles)
        unsigned a1f[2][4], a2f[2][4];
        #pragma unroll
        for (int mi = 0; mi < 2; mi++) {
            ldsm4(a1f[mi][0], a1f[mi][1], a1f[mi][2], a1f[mi][3],
                  sbase + SM_A1 + aoff + mi * (16 * RSTR));
            ldsm4(a2f[mi][0], a2f[mi][1], a2f[mi][2], a2f[mi][3],
                  sbase + SM_A2 + aoff + mi * (16 * RSTR));
        }
        // B fragments: 4 ldsm.x4 per slice, each covers 2 ni tiles
        unsigned b1f[8][2], b2f[8][2];
        #pragma unroll
        for (int p = 0; p < 4; p++) {
            ldsm4(b1f[2 * p][0], b1f[2 * p][1], b1f[2 * p + 1][0], b1f[2 * p + 1][1],
                  sbase + SM_B1 + boff + p * (16 * RSTR));
            ldsm4(b2f[2 * p][0], b2f[2 * p][1], b2f[2 * p + 1][0], b2f[2 * p + 1][1],
                  sbase + SM_B2 + boff + p * (16 * RSTR));
        }
        #pragma unroll
        for (int mi = 0; mi < 2; mi++) {
            #pragma unroll
            for (int ni = 0; ni < 8; ni++) {
                mma_s8(P1[mi][ni], a1f[mi], b1f[ni][0], b1f[ni][1]);
                mma_s8(Pc[mi][ni], a1f[mi], b2f[ni][0], b2f[ni][1]);
                mma_s8(Pc[mi][ni], a2f[mi], b1f[ni][0], b1f[ni][1]);
            }
        }
    }

    // ---- epilogue: combine slices, bias + relu, row-max for next layer ----
    const int gr2 = lane >> 2;
    const int gc2 = (lane & 3) * 2;
    #pragma unroll
    for (int mi = 0; mi < 2; mi++) {
        const int rb = row0 + wm * 32 + mi * 16 + gr2;
        float rmax[2] = {0.f, 0.f};
        #pragma unroll
        for (int h = 0; h < 2; h++) {
            const int r = rb + h * 8;
            if (r >= NN) continue;
            const float sr = fmaxf(fmaxf(g_sagg[r], mxin[r]), 1e-30f) * (1.0f / 127.0f);
            float* orow = out + (size_t)r * DD;
            #pragma unroll
            for (int ni = 0; ni < 8; ni++) {
                const int c = wn * 64 + ni * 8 + gc2;
                float2 tc = *(const float2*)(g_tm + c);
                float2 bv = *(const float2*)(bias + c);
                float f0 = (float)P1[mi][ni][h * 2 + 0] + (float)Pc[mi][ni][h * 2 + 0] * 0.00390625f;
                float f1 = (float)P1[mi][ni][h * 2 + 1] + (float)Pc[mi][ni][h * 2 + 1] * 0.00390625f;
                float v0 = f0 * sr * tc.x + bv.x;
                float v1 = f1 * sr * tc.y + bv.y;
                if (do_relu) { v0 = fmaxf(v0, 0.f); v1 = fmaxf(v1, 0.f); }
                *(float2*)(orow + c) = make_float2(v0, v1);
                rmax[h] = fmaxf(rmax[h], fmaxf(v0, v1));
            }
        }
        if (mxout_sel > 0) {
            #pragma unroll
            for (int h = 0; h < 2; h++) {
                float m = rmax[h];
                m = fmaxf(m, __shfl_xor_sync(0xffffffffu, m, 1));
                m = fmaxf(m, __shfl_xor_sync(0xffffffffu, m, 2));
                const int r = rb + h * 8;
                if ((lane & 3) == 0 && r < NN)
                    atomicMax((unsigned*)&mxout[r], __float_as_uint(m));
            }
        }
    }
}

// ---------------- launcher ----------------
extern "C" void kernel_launch(void* const* d_in, const int* in_sizes, int n_in,
                              void* d_out, int out_size) {
    (void)in_sizes; (void)n_in; (void)out_size;
    const void* edge = d_in[0];
    const float* x0 = (const float*)d_in[1];
    const float* Wl[3] = {(const float*)d_in[2], (const float*)d_in[5], (const float*)d_in[8]};
    const float* Wr[3] = {(const float*)d_in[3], (const float*)d_in[6], (const float*)d_in[9]};
    const float* bb[3] = {(const float*)d_in[4], (const float*)d_in[7], (const float*)d_in[10]};
    float* out = (float*)d_out;

    static int smem_set = 0;
    if (!smem_set) {
        cudaFuncSetAttribute(gemm_i8_kernel, cudaFuncAttributeMaxDynamicSharedMemorySize, SM_TOT);
        smem_set = 1;
    }

    const int TB = 256;
    const int ecnt = (EE + TB - 1) / TB;
    const int ncnt = (NN + TB - 1) / TB;
    const int ggrid = (NN + 63) / 64;
    const int agrid = (NN * 32 + TB - 1) / TB;

    detect_kernel<<<1, 32>>>((const unsigned int*)edge);
    convert_kernel<<<ecnt, TB>>>(edge);
    zero_deg_kernel<<<ncnt, TB>>>();
    deg_kernel<<<ecnt, TB>>>();
    invdeg_kernel<<<ncnt, TB>>>();
    scanA_kernel<<<NB, 1024>>>();
    scanB_kernel<<<1, 32>>>();
    scanC_kernel<<<NB, 1024>>>();
    fill_kernel<<<ecnt, TB>>>();
    maxabs0_kernel<<<agrid, TB>>>(x0);

    // layer 1: in x0 (mx0), out g_x1 (+mxA), relu
    quantB_kernel<<<32, TB>>>(Wl[0], Wr[0]);
    aggregate_kernel<<<agrid, TB>>>(x0, 0);
    zero_mx_kernel<<<ncnt, TB>>>(1);
    gemm_i8_kernel<<<ggrid, TB, SM_TOT>>>(x0, 0, nullptr, 1, bb[0], 1, 0, 1);

    // layer 2: in g_x1 (mxA), out g_x2 (+mxB), relu
    quantB_kernel<<<32, TB>>>(Wl[1], Wr[1]);
    aggregate_kernel<<<agrid, TB>>>(nullptr, 1);
    zero_mx_kernel<<<ncnt, TB>>>(2);
    gemm_i8_kernel<<<ggrid, TB, SM_TOT>>>(nullptr, 1, nullptr, 2, bb[1], 1, 1, 2);

    // layer 3: in g_x2 (mxB), out d_out, no relu, no mxout
    quantB_kernel<<<32, TB>>>(Wl[2], Wr[2]);
    aggregate_kernel<<<agrid, TB>>>(nullptr, 2);
    gemm_i8_kernel<<<ggrid, TB, SM_TOT>>>(nullptr, 2, out, 0, bb[2], 0, 2, 0);
}

// round 7
// speedup vs baseline: 3.0043x; 3.0043x over previous
#include <cuda_runtime.h>
#include <cuda_fp16.h>

#define NN 100000
#define DD 256
#define EE 300000
#define NB 98   // ceil(NN/1024)

typedef unsigned long long ull;

// ---------------- scratch ----------------
__device__ __align__(16) float g_acc[NN * DD];
__device__ __align__(16) float g_x1[NN * DD];
__device__ __align__(16) float g_x2[NN * DD];
__device__ int   g_degi[NN];
__device__ float g_invdeg[NN];
__device__ int   g_off[NN];
__device__ int   g_cursor[NN];
__device__ int   g_csr[EE];
__device__ int   g_src[EE];
__device__ int   g_dst[EE];
__device__ int   g_is64;
__device__ int   g_bsum[NB];
__device__ int   g_bsumex[NB];
__device__ __align__(16) __half g_bh[256 * 512];   // W fp16: [m][k], k-major

// ---------------- index dtype detection + conversion ----------------
__global__ void detect_kernel(const unsigned int* __restrict__ w) {
    if (threadIdx.x == 0 && blockIdx.x == 0) {
        unsigned int s = 0;
        #pragma unroll 1
        for (int i = 1; i < 256; i += 2) s |= w[i];
        g_is64 = (s == 0u) ? 1 : 0;
    }
}

__global__ void convert_kernel(const void* __restrict__ edge) {
    int e = blockIdx.x * blockDim.x + threadIdx.x;
    if (e >= EE) return;
    if (g_is64) {
        const long long* p = (const long long*)edge;
        g_src[e] = (int)p[e];
        g_dst[e] = (int)p[EE + e];
    } else {
        const int* p = (const int*)edge;
        g_src[e] = p[e];
        g_dst[e] = p[EE + e];
    }
}

// ---------------- degree + CSR build ----------------
__global__ void zero_deg_kernel() {
    int n = blockIdx.x * blockDim.x + threadIdx.x;
    if (n < NN) g_degi[n] = 0;
}
__global__ void deg_kernel() {
    int e = blockIdx.x * blockDim.x + threadIdx.x;
    if (e < EE) atomicAdd(&g_degi[g_dst[e]], 1);
}
__global__ void invdeg_kernel() {
    int n = blockIdx.x * blockDim.x + threadIdx.x;
    if (n < NN) g_invdeg[n] = 1.0f / fmaxf((float)g_degi[n], 1.0f);
}

__global__ void scanA_kernel() {
    __shared__ int sh[1024];
    int t = threadIdx.x;
    int n = blockIdx.x * 1024 + t;
    int v = (n < NN) ? g_degi[n] : 0;
    sh[t] = v;
    __syncthreads();
    #pragma unroll
    for (int off = 512; off > 0; off >>= 1) {
        if (t < off) sh[t] += sh[t + off];
        __syncthreads();
    }
    if (t == 0) g_bsum[blockIdx.x] = sh[0];
}

__global__ void scanB_kernel() {
    if (threadIdx.x == 0 && blockIdx.x == 0) {
        int acc = 0;
        for (int i = 0; i < NB; i++) {
            g_bsumex[i] = acc;
            acc += g_bsum[i];
        }
    }
}

__global__ void scanC_kernel() {
    __shared__ int sh[1024];
    int t = threadIdx.x;
    int n = blockIdx.x * 1024 + t;
    int v = (n < NN) ? g_degi[n] : 0;
    sh[t] = v;
    __syncthreads();
    #pragma unroll
    for (int off = 1; off < 1024; off <<= 1) {
        int x = (t >= off) ? sh[t - off] : 0;
        __syncthreads();
        sh[t] += x;
        __syncthreads();
    }
    if (n < NN) {
        int ex = g_bsumex[blockIdx.x] + sh[t] - v;
        g_off[n] = ex;
        g_cursor[n] = ex;
    }
}

__global__ void fill_kernel() {
    int e = blockIdx.x * blockDim.x + threadIdx.x;
    if (e >= EE) return;
    int pos = atomicAdd(&g_cursor[g_dst[e]], 1);
    g_csr[pos] = g_src[e];
}

// ---------------- aggregation: warp per node, CSR gather-sum ----------------
__global__ __launch_bounds__(256) void aggregate_kernel(const float* __restrict__ xext, int xsel) {
    const float* xin = (xsel == 0) ? xext : ((xsel == 1) ? g_x1 : g_x2);
    int warp = (blockIdx.x * blockDim.x + threadIdx.x) >> 5;
    if (warp >= NN) return;
    int lane = threadIdx.x & 31;
    int start = g_off[warp];
    int cnt = g_degi[warp];
    float4 a0 = make_float4(0.f, 0.f, 0.f, 0.f);
    float4 a1 = a0;
    #pragma unroll 1
    for (int i = 0; i < cnt; i++) {
        int s = g_csr[start + i];
        const float4* r = (const float4*)(xin + (size_t)s * DD);
        float4 v0 = r[lane];
        float4 v1 = r[lane + 32];
        a0.x += v0.x; a0.y += v0.y; a0.z += v0.z; a0.w += v0.w;
        a1.x += v1.x; a1.y += v1.y; a1.z += v1.z; a1.w += v1.w;
    }
    float4* o = (float4*)(g_acc + (size_t)warp * DD);
    o[lane] = a0;
    o[lane + 32] = a1;
}

// ---------------- weight convert (fp32 -> fp16) ----------------
__global__ void convw_kernel(const float* __restrict__ Wl, const float* __restrict__ Wr) {
    int i = blockIdx.x * blockDim.x + threadIdx.x;
    if (i >= 256 * 512) return;
    int m = i >> 9, k = i & 511;
    float w = (k < 256) ? Wl[m * 256 + k] : Wr[m * 256 + (k - 256)];
    g_bh[i] = __float2half_rn(w);
}

// ---------------- mma / async-copy helpers (baseline PTX) ----------------
__device__ __forceinline__ unsigned sm_u32(const void* p) {
    unsigned r;
    asm("{ .reg .u64 t; cvta.to.shared.u64 t, %1; cvt.u32.u64 %0, t; }" : "=r"(r) : "l"(p));
    return r;
}
__device__ __forceinline__ void sts128(unsigned a, unsigned x, unsigned y, unsigned z, unsigned w) {
    asm volatile("st.shared.v4.b32 [%0], {%1,%2,%3,%4};" :: "r"(a), "r"(x), "r"(y), "r"(z), "r"(w));
}
__device__ __forceinline__ void cpasync16(unsigned smem, const void* g) {
    asm volatile("cp.async.cg.shared.global [%0], [%1], 16;" :: "r"(smem), "l"(g));
}
__device__ __forceinline__ void cpcommit() { asm volatile("cp.async.commit_group;"); }
__device__ __forceinline__ void cpwait0() { asm volatile("cp.async.wait_group 0;"); }
__device__ __forceinline__ void ldsm4(unsigned& r0, unsigned& r1, unsigned& r2, unsigned& r3, unsigned a) {
    asm volatile("ldmatrix.sync.aligned.m8n8.x4.shared.b16 {%0,%1,%2,%3}, [%4];"
                 : "=r"(r0), "=r"(r1), "=r"(r2), "=r"(r3) : "r"(a));
}
__device__ __forceinline__ void mma16816(float* c, const unsigned* a, unsigned b0, unsigned b1) {
    asm volatile(
        "mma.sync.aligned.m16n8k16.row.col.f32.f16.f16.f32 "
        "{%0,%1,%2,%3}, {%4,%5,%6,%7}, {%8,%9}, {%0,%1,%2,%3};"
        : "+f"(c[0]), "+f"(c[1]), "+f"(c[2]), "+f"(c[3])
        : "r"(a[0]), "r"(a[1]), "r"(a[2]), "r"(a[3]), "r"(b0), "r"(b1));
}
__device__ __forceinline__ unsigned h2u(__half2 v) {
    unsigned r;
    memcpy(&r, &v, 4);
    return r;
}

// smem layout: rows padded to 80B (gcd(80,128)=16 -> conflict-free ldmatrix)
#define ASTR 80
#define SM_A 10240             // 128 rows * 80B
#define SM_B 20480             // 256 rows * 80B
#define SM_STG (2*SM_A + SM_B)      // one stage: AH|AL|BH = 40960
#define SM_TOT (2*SM_STG)           // double buffered = 81920

// ---------------- fused layer GEMM (mma.sync fp16, A 2-term split, B single) ----------------
// out[r, m] = relu?( sum_k A[r,k] * W[m,k] + b[m] ), A = [invdeg*acc | xin] (K=512)
__global__ __launch_bounds__(512) void gemm_mma_kernel(
    const float* __restrict__ xext, int xsel,
    float* __restrict__ oext, int osel,
    const float* __restrict__ bias, int do_relu)
{
    extern __shared__ char smem[];
    const float* xin = (xsel == 0) ? xext : ((xsel == 1) ? g_x1 : g_x2);
    float* out = (osel == 0) ? oext : ((osel == 1) ? g_x1 : g_x2);

    const unsigned su = sm_u32(smem);

    const int tid = threadIdx.x;
    const int wid = tid >> 5;
    const int lane = tid & 31;
    const int wm = wid & 1;
    const int wn = wid >> 1;
    const int row0 = blockIdx.x * 128;

    // A loader geometry
    const int arow = tid >> 2;
    const int akq = tid & 3;
    const int gr = row0 + arow;
    const bool rok = gr < NN;
    const float invd = rok ? g_invdeg[gr] : 0.f;
    const float* aggrow = g_acc + (size_t)(rok ? gr : 0) * DD;
    const float* xrow = xin + (size_t)(rok ? gr : 0) * DD;

    // B loader geometry (cp.async): thread -> half of one W row chunk
    const int brow = tid >> 1;
    const int bkh = (tid & 1) * 16;

    // ldmatrix fragment addresses (stage-relative)
    const unsigned aoff = (unsigned)((wm * 64 + (lane & 15)) * ASTR + (lane >> 4) * 16);
    const unsigned boff = (unsigned)((wn * 32 + ((lane >> 4) & 1) * 8 + (lane & 7)) * ASTR
                                     + ((lane >> 3) & 1) * 16);

    float acc[4][4][4];
    #pragma unroll
    for (int i = 0; i < 4; i++)
        #pragma unroll
        for (int j = 0; j < 4; j++)
            #pragma unroll
            for (int q = 0; q < 4; q++) acc[i][j][q] = 0.f;

    float4 pa0, pa1;   // prefetched A chunk (8 fp32)
    float psc;

    auto ldA = [&](int ck) {
        const int side = ck >> 3;
        const float* s = (side ? xrow : aggrow) + (ck & 7) * 32 + akq * 8;
        psc = side ? 1.f : invd;
        if (rok) {
            pa0 = *(const float4*)(s);
            pa1 = *(const float4*)(s + 4);
        } else {
            pa0 = make_float4(0.f, 0.f, 0.f, 0.f);
            pa1 = pa0;
        }
    };
    auto stsA = [&](int stg) {
        float v[8] = {pa0.x * psc, pa0.y * psc, pa0.z * psc, pa0.w * psc,
                      pa1.x * psc, pa1.y * psc, pa1.z * psc, pa1.w * psc};
        unsigned h[4], l[4];
        #pragma unroll
        for (int i = 0; i < 4; i++) {
            __half hx = __float2half_rn(v[2 * i]);
            __half hy = __float2half_rn(v[2 * i + 1]);
            __half lx = __float2half_rn(v[2 * i] - __half2float(hx));
            __half ly = __float2half_rn(v[2 * i + 1] - __half2float(hy));
            h[i] = h2u(__halves2half2(hx, hy));
            l[i] = h2u(__halves2half2(lx, ly));
        }
        unsigned base = su + (unsigned)stg * SM_STG;
        unsigned off = (unsigned)(arow * ASTR + akq * 16);
        sts128(base + off, h[0], h[1], h[2], h[3]);
        sts128(base + SM_A + off, l[0], l[1], l[2], l[3]);
    };
    auto cpB = [&](int ck, int stg) {
        unsigned base = su + (unsigned)stg * SM_STG + 2 * SM_A;
        unsigned off = (unsigned)(brow * ASTR + bkh * 2);
        size_t go = (size_t)brow * 512 + ck * 32 + bkh;
        cpasync16(base + off, g_bh + go);
        cpasync16(base + off + 16, g_bh + go + 8);
        cpcommit();
    };

    // prologue: fill stage 0, prefetch A for chunk 1
    ldA(0);
    stsA(0);
    cpB(0, 0);
    ldA(1);

    #pragma unroll 1
    for (int ck = 0; ck < 16; ck++) {
        const int s = ck & 1;
        cpwait0();          // B[ck] arrived
        __syncthreads();    // A[ck] visible; all warps done with buffer s^1

        if (ck < 15) {
            stsA(s ^ 1);
            cpB(ck + 1, s ^ 1);
        }
        if (ck < 14) ldA(ck + 2);

        const unsigned sbase = su + (unsigned)s * SM_STG;
        const unsigned suAH = sbase;
        const unsigned suAL = sbase + SM_A;
        const unsigned suBH = sbase + 2 * SM_A;

        #pragma unroll
        for (int ks = 0; ks < 2; ks++) {
            const unsigned kb = (unsigned)(ks * 32);
            unsigned bh[4][2];
            #pragma unroll
            for (int p = 0; p < 2; p++) {
                ldsm4(bh[2 * p][0], bh[2 * p][1], bh[2 * p + 1][0], bh[2 * p + 1][1],
                      suBH + boff + p * (16 * ASTR) + kb);
            }
            #pragma unroll
            for (int mi = 0; mi < 4; mi++) {
                unsigned af[4];
                ldsm4(af[0], af[1], af[2], af[3], suAH + aoff + mi * (16 * ASTR) + kb);
                #pragma unroll
                for (int ni = 0; ni < 4; ni++) mma16816(acc[mi][ni], af, bh[ni][0], bh[ni][1]);
                ldsm4(af[0], af[1], af[2], af[3], suAL + aoff + mi * (16 * ASTR) + kb);
                #pragma unroll
                for (int ni = 0; ni < 4; ni++) mma16816(acc[mi][ni], af, bh[ni][0], bh[ni][1]);
            }
        }
    }

    // ---- epilogue: bias + relu, direct gmem stores ----
    const int gr2 = lane >> 2;
    const int gc2 = (lane & 3) * 2;
    #pragma unroll
    for (int mi = 0; mi < 4; mi++) {
        const int rbase = row0 + wm * 64 + mi * 16 + gr2;
        #pragma unroll
        for (int h = 0; h < 2; h++) {
            const int r = rbase + h * 8;
            if (r < NN) {
                float* orow = out + (size_t)r * DD;
                #pragma unroll
                for (int ni = 0; ni < 4; ni++) {
                    const int c = wn * 32 + ni * 8 + gc2;
                    float2 bv = *(const float2*)(bias + c);
                    float v0 = acc[mi][ni][h * 2 + 0] + bv.x;
                    float v1 = acc[mi][ni][h * 2 + 1] + bv.y;
                    if (do_relu) { v0 = fmaxf(v0, 0.f); v1 = fmaxf(v1, 0.f); }
                    *(float2*)(orow + c) = make_float2(v0, v1);
                }
            }
        }
    }
}

// ---------------- launcher ----------------
extern "C" void kernel_launch(void* const* d_in, const int* in_sizes, int n_in,
                              void* d_out, int out_size) {
    (void)in_sizes; (void)n_in; (void)out_size;
    const void* edge = d_in[0];
    const float* x0 = (const float*)d_in[1];
    const float* Wl[3] = {(const float*)d_in[2], (const float*)d_in[5], (const float*)d_in[8]};
    const float* Wr[3] = {(const float*)d_in[3], (const float*)d_in[6], (const float*)d_in[9]};
    const float* bb[3] = {(const float*)d_in[4], (const float*)d_in[7], (const float*)d_in[10]};
    float* out = (float*)d_out;

    static int smem_set = 0;
    if (!smem_set) {
        cudaFuncSetAttribute(gemm_mma_kernel, cudaFuncAttributeMaxDynamicSharedMemorySize, SM_TOT);
        smem_set = 1;
    }

    const int TB = 256;
    const int ecnt = (EE + TB - 1) / TB;
    const int ncnt = (NN + TB - 1) / TB;
    const int wcnt = (256 * 512 + TB - 1) / TB;
    const int ggrid = (NN + 127) / 128;
    const int agrid = (NN * 32 + TB - 1) / TB;

    detect_kernel<<<1, 32>>>((const unsigned int*)edge);
    convert_kernel<<<ecnt, TB>>>(edge);
    zero_deg_kernel<<<ncnt, TB>>>();
    deg_kernel<<<ecnt, TB>>>();
    invdeg_kernel<<<ncnt, TB>>>();
    scanA_kernel<<<NB, 1024>>>();
    scanB_kernel<<<1, 32>>>();
    scanC_kernel<<<NB, 1024>>>();
    fill_kernel<<<ecnt, TB>>>();

    // layer 1
    convw_kernel<<<wcnt, TB>>>(Wl[0], Wr[0]);
    aggregate_kernel<<<agrid, TB>>>(x0, 0);
    gemm_mma_kernel<<<ggrid, 512, SM_TOT>>>(x0, 0, nullptr, 1, bb[0], 1);

    // layer 2
    convw_kernel<<<wcnt, TB>>>(Wl[1], Wr[1]);
    aggregate_kernel<<<agrid, TB>>>(nullptr, 1);
    gemm_mma_kernel<<<ggrid, 512, SM_TOT>>>(nullptr, 1, nullptr, 2, bb[1], 1);

    // layer 3
    convw_kernel<<<wcnt, TB>>>(Wl[2], Wr[2]);
    aggregate_kernel<<<agrid, TB>>>(nullptr, 2);
    gemm_mma_kernel<<<ggrid, 512, SM_TOT>>>(nullptr, 2, out, 0, bb[2], 0);
}

// round 8
// speedup vs baseline: 3.9903x; 1.3282x over previous
#include <cuda_runtime.h>
#include <cuda_fp16.h>

#define NN 100000
#define DD 256
#define EE 300000
#define NB 98   // ceil(NN/1024)

typedef unsigned long long ull;

// ---------------- scratch ----------------
__device__ __align__(16) float g_acc[NN * DD];
__device__ __align__(16) float g_x1[NN * DD];
__device__ __align__(16) float g_x2[NN * DD];
__device__ int   g_degi[NN];
__device__ float g_invdeg[NN];
__device__ int   g_off[NN];
__device__ int   g_cursor[NN];
__device__ int   g_csr[EE];
__device__ int   g_src[EE];
__device__ int   g_dst[EE];
__device__ int   g_is64;
__device__ int   g_bsum[NB];
__device__ int   g_bsumex[NB];
__device__ __align__(16) __half g_bh[256 * 512];   // W fp16: [m][k], k-major

// ---------------- index dtype detection + conversion ----------------
__global__ void detect_kernel(const unsigned int* __restrict__ w) {
    if (threadIdx.x == 0 && blockIdx.x == 0) {
        unsigned int s = 0;
        #pragma unroll 1
        for (int i = 1; i < 256; i += 2) s |= w[i];
        g_is64 = (s == 0u) ? 1 : 0;
    }
}

__global__ void convert_kernel(const void* __restrict__ edge) {
    int e = blockIdx.x * blockDim.x + threadIdx.x;
    if (e >= EE) return;
    if (g_is64) {
        const long long* p = (const long long*)edge;
        g_src[e] = (int)p[e];
        g_dst[e] = (int)p[EE + e];
    } else {
        const int* p = (const int*)edge;
        g_src[e] = p[e];
        g_dst[e] = p[EE + e];
    }
}

// ---------------- degree + CSR build ----------------
__global__ void zero_deg_kernel() {
    int n = blockIdx.x * blockDim.x + threadIdx.x;
    if (n < NN) g_degi[n] = 0;
}
__global__ void deg_kernel() {
    int e = blockIdx.x * blockDim.x + threadIdx.x;
    if (e < EE) atomicAdd(&g_degi[g_dst[e]], 1);
}
__global__ void invdeg_kernel() {
    int n = blockIdx.x * blockDim.x + threadIdx.x;
    if (n < NN) g_invdeg[n] = 1.0f / fmaxf((float)g_degi[n], 1.0f);
}

__global__ void scanA_kernel() {
    __shared__ int sh[1024];
    int t = threadIdx.x;
    int n = blockIdx.x * 1024 + t;
    int v = (n < NN) ? g_degi[n] : 0;
    sh[t] = v;
    __syncthreads();
    #pragma unroll
    for (int off = 512; off > 0; off >>= 1) {
        if (t < off) sh[t] += sh[t + off];
        __syncthreads();
    }
    if (t == 0) g_bsum[blockIdx.x] = sh[0];
}

__global__ void scanB_kernel() {
    if (threadIdx.x == 0 && blockIdx.x == 0) {
        int acc = 0;
        for (int i = 0; i < NB; i++) {
            g_bsumex[i] = acc;
            acc += g_bsum[i];
        }
    }
}

__global__ void scanC_kernel() {
    __shared__ int sh[1024];
    int t = threadIdx.x;
    int n = blockIdx.x * 1024 + t;
    int v = (n < NN) ? g_degi[n] : 0;
    sh[t] = v;
    __syncthreads();
    #pragma unroll
    for (int off = 1; off < 1024; off <<= 1) {
        int x = (t >= off) ? sh[t - off] : 0;
        __syncthreads();
        sh[t] += x;
        __syncthreads();
    }
    if (n < NN) {
        int ex = g_bsumex[blockIdx.x] + sh[t] - v;
        g_off[n] = ex;
        g_cursor[n] = ex;
    }
}

__global__ void fill_kernel() {
    int e = blockIdx.x * blockDim.x + threadIdx.x;
    if (e >= EE) return;
    int pos = atomicAdd(&g_cursor[g_dst[e]], 1);
    g_csr[pos] = g_src[e];
}

// ---------------- aggregation: warp per node, CSR gather-MEAN (invdeg folded in) ----------------
__global__ __launch_bounds__(256) void aggregate_kernel(const float* __restrict__ xext, int xsel) {
    const float* xin = (xsel == 0) ? xext : ((xsel == 1) ? g_x1 : g_x2);
    int warp = (blockIdx.x * blockDim.x + threadIdx.x) >> 5;
    if (warp >= NN) return;
    int lane = threadIdx.x & 31;
    int start = g_off[warp];
    int cnt = g_degi[warp];
    float4 a0 = make_float4(0.f, 0.f, 0.f, 0.f);
    float4 a1 = a0;
    #pragma unroll 1
    for (int i = 0; i < cnt; i++) {
        int s = g_csr[start + i];
        const float4* r = (const float4*)(xin + (size_t)s * DD);
        float4 v0 = r[lane];
        float4 v1 = r[lane + 32];
        a0.x += v0.x; a0.y += v0.y; a0.z += v0.z; a0.w += v0.w;
        a1.x += v1.x; a1.y += v1.y; a1.z += v1.z; a1.w += v1.w;
    }
    float id = g_invdeg[warp];
    a0.x *= id; a0.y *= id; a0.z *= id; a0.w *= id;
    a1.x *= id; a1.y *= id; a1.z *= id; a1.w *= id;
    float4* o = (float4*)(g_acc + (size_t)warp * DD);
    o[lane] = a0;
    o[lane + 32] = a1;
}

// ---------------- weight convert (fp32 -> fp16) ----------------
__global__ void convw_kernel(const float* __restrict__ Wl, const float* __restrict__ Wr) {
    int i = blockIdx.x * blockDim.x + threadIdx.x;
    if (i >= 256 * 512) return;
    int m = i >> 9, k = i & 511;
    float w = (k < 256) ? Wl[m * 256 + k] : Wr[m * 256 + (k - 256)];
    g_bh[i] = __float2half_rn(w);
}

// ---------------- mma / async-copy helpers (baseline PTX) ----------------
__device__ __forceinline__ unsigned sm_u32(const void* p) {
    unsigned r;
    asm("{ .reg .u64 t; cvta.to.shared.u64 t, %1; cvt.u32.u64 %0, t; }" : "=r"(r) : "l"(p));
    return r;
}
__device__ __forceinline__ void sts128(unsigned a, unsigned x, unsigned y, unsigned z, unsigned w) {
    asm volatile("st.shared.v4.b32 [%0], {%1,%2,%3,%4};" :: "r"(a), "r"(x), "r"(y), "r"(z), "r"(w));
}
__device__ __forceinline__ void cpasync16(unsigned smem, const void* g) {
    asm volatile("cp.async.cg.shared.global [%0], [%1], 16;" :: "r"(smem), "l"(g));
}
__device__ __forceinline__ void cpcommit() { asm volatile("cp.async.commit_group;"); }
__device__ __forceinline__ void cpwait0() { asm volatile("cp.async.wait_group 0;"); }
__device__ __forceinline__ void ldsm4(unsigned& r0, unsigned& r1, unsigned& r2, unsigned& r3, unsigned a) {
    asm volatile("ldmatrix.sync.aligned.m8n8.x4.shared.b16 {%0,%1,%2,%3}, [%4];"
                 : "=r"(r0), "=r"(r1), "=r"(r2), "=r"(r3) : "r"(a));
}
__device__ __forceinline__ void mma16816(float* c, const unsigned* a, unsigned b0, unsigned b1) {
    asm volatile(
        "mma.sync.aligned.m16n8k16.row.col.f32.f16.f16.f32 "
        "{%0,%1,%2,%3}, {%4,%5,%6,%7}, {%8,%9}, {%0,%1,%2,%3};"
        : "+f"(c[0]), "+f"(c[1]), "+f"(c[2]), "+f"(c[3])
        : "r"(a[0]), "r"(a[1]), "r"(a[2]), "r"(a[3]), "r"(b0), "r"(b1));
}
__device__ __forceinline__ unsigned h2u(__half2 v) {
    unsigned r;
    memcpy(&r, &v, 4);
    return r;
}

// smem layout: rows padded to 80B (gcd(80,128)=16 -> conflict-free ldmatrix)
#define ASTR 80
#define SM_A 10240             // 128 rows * 80B
#define SM_B 20480             // 256 rows * 80B
#define SM_STG (SM_A + SM_B)        // one stage: A|B = 30720
#define SM_TOT (2*SM_STG)           // double buffered = 61440

// ---------------- fused layer GEMM (mma.sync fp16, single term) ----------------
// out[r, m] = relu?( sum_k A[r,k] * W[m,k] + b[m] ), A = [mean_agg | xin] (K=512)
__global__ __launch_bounds__(512) void gemm_mma_kernel(
    const float* __restrict__ xext, int xsel,
    float* __restrict__ oext, int osel,
    const float* __restrict__ bias, int do_relu)
{
    extern __shared__ char smem[];
    const float* xin = (xsel == 0) ? xext : ((xsel == 1) ? g_x1 : g_x2);
    float* out = (osel == 0) ? oext : ((osel == 1) ? g_x1 : g_x2);

    const unsigned su = sm_u32(smem);

    const int tid = threadIdx.x;
    const int wid = tid >> 5;
    const int lane = tid & 31;
    const int wm = wid & 1;
    const int wn = wid >> 1;
    const int row0 = blockIdx.x * 128;

    // A loader geometry
    const int arow = tid >> 2;
    const int akq = tid & 3;
    const int gr = row0 + arow;
    const bool rok = gr < NN;
    const float* aggrow = g_acc + (size_t)(rok ? gr : 0) * DD;
    const float* xrow = xin + (size_t)(rok ? gr : 0) * DD;

    // B loader geometry (cp.async)
    const int brow = tid >> 1;
    const int bkh = (tid & 1) * 16;

    // ldmatrix fragment addresses (stage-relative)
    const unsigned aoff = (unsigned)((wm * 64 + (lane & 15)) * ASTR + (lane >> 4) * 16);
    const unsigned boff = (unsigned)((wn * 32 + ((lane >> 4) & 1) * 8 + (lane & 7)) * ASTR
                                     + ((lane >> 3) & 1) * 16);

    float acc[4][4][4];
    #pragma unroll
    for (int i = 0; i < 4; i++)
        #pragma unroll
        for (int j = 0; j < 4; j++)
            #pragma unroll
            for (int q = 0; q < 4; q++) acc[i][j][q] = 0.f;

    float4 pa0, pa1;   // prefetched A chunk (8 fp32)

    auto ldA = [&](int ck) {
        const int side = ck >> 3;
        const float* s = (side ? xrow : aggrow) + (ck & 7) * 32 + akq * 8;
        if (rok) {
            pa0 = *(const float4*)(s);
            pa1 = *(const float4*)(s + 4);
        } else {
            pa0 = make_float4(0.f, 0.f, 0.f, 0.f);
            pa1 = pa0;
        }
    };
    auto stsA = [&](int stg) {
        unsigned h[4];
        h[0] = h2u(__floats2half2_rn(pa0.x, pa0.y));
        h[1] = h2u(__floats2half2_rn(pa0.z, pa0.w));
        h[2] = h2u(__floats2half2_rn(pa1.x, pa1.y));
        h[3] = h2u(__floats2half2_rn(pa1.z, pa1.w));
        unsigned base = su + (unsigned)stg * SM_STG;
        unsigned off = (unsigned)(arow * ASTR + akq * 16);
        sts128(base + off, h[0], h[1], h[2], h[3]);
    };
    auto cpB = [&](int ck, int stg) {
        unsigned base = su + (unsigned)stg * SM_STG + SM_A;
        unsigned off = (unsigned)(brow * ASTR + bkh * 2);
        size_t go = (size_t)brow * 512 + ck * 32 + bkh;
        cpasync16(base + off, g_bh + go);
        cpasync16(base + off + 16, g_bh + go + 8);
        cpcommit();
    };

    // prologue: fill stage 0, prefetch A for chunk 1
    ldA(0);
    stsA(0);
    cpB(0, 0);
    ldA(1);

    #pragma unroll 1
    for (int ck = 0; ck < 16; ck++) {
        const int s = ck & 1;
        cpwait0();          // B[ck] arrived
        __syncthreads();    // A[ck] visible; all warps done with buffer s^1

        if (ck < 15) {
            stsA(s ^ 1);
            cpB(ck + 1, s ^ 1);
        }
        if (ck < 14) ldA(ck + 2);

        const unsigned sbase = su + (unsigned)s * SM_STG;
        const unsigned suA = sbase;
        const unsigned suB = sbase + SM_A;

        #pragma unroll
        for (int ks = 0; ks < 2; ks++) {
            const unsigned kb = (unsigned)(ks * 32);
            unsigned bh[4][2];
            #pragma unroll
            for (int p = 0; p < 2; p++) {
                ldsm4(bh[2 * p][0], bh[2 * p][1], bh[2 * p + 1][0], bh[2 * p + 1][1],
                      suB + boff + p * (16 * ASTR) + kb);
            }
            #pragma unroll
            for (int mi = 0; mi < 4; mi++) {
                unsigned af[4];
                ldsm4(af[0], af[1], af[2], af[3], suA + aoff + mi * (16 * ASTR) + kb);
                #pragma unroll
                for (int ni = 0; ni < 4; ni++) mma16816(acc[mi][ni], af, bh[ni][0], bh[ni][1]);
            }
        }
    }

    // ---- epilogue: bias + relu, direct gmem stores ----
    const int gr2 = lane >> 2;
    const int gc2 = (lane & 3) * 2;
    #pragma unroll
    for (int mi = 0; mi < 4; mi++) {
        const int rbase = row0 + wm * 64 + mi * 16 + gr2;
        #pragma unroll
        for (int h = 0; h < 2; h++) {
            const int r = rbase + h * 8;
            if (r < NN) {
                float* orow = out + (size_t)r * DD;
                #pragma unroll
                for (int ni = 0; ni < 4; ni++) {
                    const int c = wn * 32 + ni * 8 + gc2;
                    float2 bv = *(const float2*)(bias + c);
                    float v0 = acc[mi][ni][h * 2 + 0] + bv.x;
                    float v1 = acc[mi][ni][h * 2 + 1] + bv.y;
                    if (do_relu) { v0 = fmaxf(v0, 0.f); v1 = fmaxf(v1, 0.f); }
                    *(float2*)(orow + c) = make_float2(v0, v1);
                }
            }
        }
    }
}

// ---------------- launcher ----------------
extern "C" void kernel_launch(void* const* d_in, const int* in_sizes, int n_in,
                              void* d_out, int out_size) {
    (void)in_sizes; (void)n_in; (void)out_size;
    const void* edge = d_in[0];
    const float* x0 = (const float*)d_in[1];
    const float* Wl[3] = {(const float*)d_in[2], (const float*)d_in[5], (const float*)d_in[8]};
    const float* Wr[3] = {(const float*)d_in[3], (const float*)d_in[6], (const float*)d_in[9]};
    const float* bb[3] = {(const float*)d_in[4], (const float*)d_in[7], (const float*)d_in[10]};
    float* out = (float*)d_out;

    static int smem_set = 0;
    if (!smem_set) {
        cudaFuncSetAttribute(gemm_mma_kernel, cudaFuncAttributeMaxDynamicSharedMemorySize, SM_TOT);
        smem_set = 1;
    }

    const int TB = 256;
    const int ecnt = (EE + TB - 1) / TB;
    const int ncnt = (NN + TB - 1) / TB;
    const int wcnt = (256 * 512 + TB - 1) / TB;
    const int ggrid = (NN + 127) / 128;
    const int agrid = (NN * 32 + TB - 1) / TB;

    detect_kernel<<<1, 32>>>((const unsigned int*)edge);
    convert_kernel<<<ecnt, TB>>>(edge);
    zero_deg_kernel<<<ncnt, TB>>>();
    deg_kernel<<<ecnt, TB>>>();
    invdeg_kernel<<<ncnt, TB>>>();
    scanA_kernel<<<NB, 1024>>>();
    scanB_kernel<<<1, 32>>>();
    scanC_kernel<<<NB, 1024>>>();
    fill_kernel<<<ecnt, TB>>>();

    // layer 1
    convw_kernel<<<wcnt, TB>>>(Wl[0], Wr[0]);
    aggregate_kernel<<<agrid, TB>>>(x0, 0);
    gemm_mma_kernel<<<ggrid, 512, SM_TOT>>>(x0, 0, nullptr, 1, bb[0], 1);

    // layer 2
    convw_kernel<<<wcnt, TB>>>(Wl[1], Wr[1]);
    aggregate_kernel<<<agrid, TB>>>(nullptr, 1);
    gemm_mma_kernel<<<ggrid, 512, SM_TOT>>>(nullptr, 1, nullptr, 2, bb[1], 1);

    // layer 3
    convw_kernel<<<wcnt, TB>>>(Wl[2], Wr[2]);
    aggregate_kernel<<<agrid, TB>>>(nullptr, 2);
    gemm_mma_kernel<<<ggrid, 512, SM_TOT>>>(nullptr, 2, out, 0, bb[2], 0);
}

// round 9
// speedup vs baseline: 4.3449x; 1.0889x over previous
#include <cuda_runtime.h>
#include <cuda_fp16.h>

#define NN 100000
#define DD 256
#define EE 300000
#define NB 98   // ceil(NN/1024)

typedef unsigned long long ull;

// ---------------- scratch (fp16 activations) ----------------
__device__ __align__(16) __half g_x0h[NN * DD];
__device__ __align__(16) __half g_x1h[NN * DD];
__device__ __align__(16) __half g_x2h[NN * DD];
__device__ __align__(16) __half g_acch[NN * DD];
__device__ int   g_degi[NN];
__device__ float g_invdeg[NN];
__device__ int   g_off[NN];
__device__ int   g_cursor[NN];
__device__ int   g_csr[EE];
__device__ int   g_src[EE];
__device__ int   g_dst[EE];
__device__ int   g_is64;
__device__ int   g_bsum[NB];
__device__ int   g_bsumex[NB];
__device__ __align__(16) __half g_bh[256 * 512];   // W fp16: [m][k], k-major

__device__ __forceinline__ unsigned h2u(__half2 v) {
    unsigned r;
    memcpy(&r, &v, 4);
    return r;
}

// ---------------- index dtype detection + conversion ----------------
__global__ void detect_kernel(const unsigned int* __restrict__ w) {
    if (threadIdx.x == 0 && blockIdx.x == 0) {
        unsigned int s = 0;
        #pragma unroll 1
        for (int i = 1; i < 256; i += 2) s |= w[i];
        g_is64 = (s == 0u) ? 1 : 0;
    }
}

__global__ void convert_kernel(const void* __restrict__ edge) {
    int e = blockIdx.x * blockDim.x + threadIdx.x;
    if (e >= EE) return;
    if (g_is64) {
        const long long* p = (const long long*)edge;
        g_src[e] = (int)p[e];
        g_dst[e] = (int)p[EE + e];
    } else {
        const int* p = (const int*)edge;
        g_src[e] = p[e];
        g_dst[e] = p[EE + e];
    }
}

// ---------------- x0 -> fp16 copy ----------------
__global__ void cvt0_kernel(const float* __restrict__ x0) {
    int i = blockIdx.x * blockDim.x + threadIdx.x;
    if (i >= NN * DD / 8) return;
    const float4* p = (const float4*)x0 + (size_t)i * 2;
    float4 v0 = p[0];
    float4 v1 = p[1];
    uint4 o;
    o.x = h2u(__floats2half2_rn(v0.x, v0.y));
    o.y = h2u(__floats2half2_rn(v0.z, v0.w));
    o.z = h2u(__floats2half2_rn(v1.x, v1.y));
    o.w = h2u(__floats2half2_rn(v1.z, v1.w));
    ((uint4*)g_x0h)[i] = o;
}

// ---------------- degree + CSR build ----------------
__global__ void zero_deg_kernel() {
    int n = blockIdx.x * blockDim.x + threadIdx.x;
    if (n < NN) g_degi[n] = 0;
}
__global__ void deg_kernel() {
    int e = blockIdx.x * blockDim.x + threadIdx.x;
    if (e < EE) atomicAdd(&g_degi[g_dst[e]], 1);
}
__global__ void invdeg_kernel() {
    int n = blockIdx.x * blockDim.x + threadIdx.x;
    if (n < NN) g_invdeg[n] = 1.0f / fmaxf((float)g_degi[n], 1.0f);
}

__global__ void scanA_kernel() {
    __shared__ int sh[1024];
    int t = threadIdx.x;
    int n = blockIdx.x * 1024 + t;
    int v = (n < NN) ? g_degi[n] : 0;
    sh[t] = v;
    __syncthreads();
    #pragma unroll
    for (int off = 512; off > 0; off >>= 1) {
        if (t < off) sh[t] += sh[t + off];
        __syncthreads();
    }
    if (t == 0) g_bsum[blockIdx.x] = sh[0];
}

__global__ void scanB_kernel() {
    if (threadIdx.x == 0 && blockIdx.x == 0) {
        int acc = 0;
        for (int i = 0; i < NB; i++) {
            g_bsumex[i] = acc;
            acc += g_bsum[i];
        }
    }
}

__global__ void scanC_kernel() {
    __shared__ int sh[1024];
    int t = threadIdx.x;
    int n = blockIdx.x * 1024 + t;
    int v = (n < NN) ? g_degi[n] : 0;
    sh[t] = v;
    __syncthreads();
    #pragma unroll
    for (int off = 1; off < 1024; off <<= 1) {
        int x = (t >= off) ? sh[t - off] : 0;
        __syncthreads();
        sh[t] += x;
        __syncthreads();
    }
    if (n < NN) {
        int ex = g_bsumex[blockIdx.x] + sh[t] - v;
        g_off[n] = ex;
        g_cursor[n] = ex;
    }
}

__global__ void fill_kernel() {
    int e = blockIdx.x * blockDim.x + threadIdx.x;
    if (e >= EE) return;
    int pos = atomicAdd(&g_cursor[g_dst[e]], 1);
    g_csr[pos] = g_src[e];
}

// ---------------- aggregation: warp per node, fp16 CSR gather-MEAN ----------------
__global__ __launch_bounds__(256) void aggregate_kernel(int xsel) {
    const __half* xin = (xsel == 0) ? g_x0h : ((xsel == 1) ? g_x1h : g_x2h);
    int warp = (blockIdx.x * blockDim.x + threadIdx.x) >> 5;
    if (warp >= NN) return;
    int lane = threadIdx.x & 31;
    int start = g_off[warp];
    int cnt = g_degi[warp];
    float a[8] = {0.f, 0.f, 0.f, 0.f, 0.f, 0.f, 0.f, 0.f};
    #pragma unroll 1
    for (int i = 0; i < cnt; i++) {
        int s = g_csr[start + i];
        uint4 v = *(const uint4*)(xin + (size_t)s * DD + lane * 8);
        __half2 h;
        float2 f;
        memcpy(&h, &v.x, 4); f = __half22float2(h); a[0] += f.x; a[1] += f.y;
        memcpy(&h, &v.y, 4); f = __half22float2(h); a[2] += f.x; a[3] += f.y;
        memcpy(&h, &v.z, 4); f = __half22float2(h); a[4] += f.x; a[5] += f.y;
        memcpy(&h, &v.w, 4); f = __half22float2(h); a[6] += f.x; a[7] += f.y;
    }
    float id = g_invdeg[warp];
    uint4 o;
    o.x = h2u(__floats2half2_rn(a[0] * id, a[1] * id));
    o.y = h2u(__floats2half2_rn(a[2] * id, a[3] * id));
    o.z = h2u(__floats2half2_rn(a[4] * id, a[5] * id));
    o.w = h2u(__floats2half2_rn(a[6] * id, a[7] * id));
    *(uint4*)(g_acch + (size_t)warp * DD + lane * 8) = o;
}

// ---------------- weight convert (fp32 -> fp16) ----------------
__global__ void convw_kernel(const float* __restrict__ Wl, const float* __restrict__ Wr) {
    int i = blockIdx.x * blockDim.x + threadIdx.x;
    if (i >= 256 * 512) return;
    int m = i >> 9, k = i & 511;
    float w = (k < 256) ? Wl[m * 256 + k] : Wr[m * 256 + (k - 256)];
    g_bh[i] = __float2half_rn(w);
}

// ---------------- mma / async-copy helpers (baseline PTX) ----------------
__device__ __forceinline__ unsigned sm_u32(const void* p) {
    unsigned r;
    asm("{ .reg .u64 t; cvta.to.shared.u64 t, %1; cvt.u32.u64 %0, t; }" : "=r"(r) : "l"(p));
    return r;
}
__device__ __forceinline__ void sts128(unsigned a, unsigned x, unsigned y, unsigned z, unsigned w) {
    asm volatile("st.shared.v4.b32 [%0], {%1,%2,%3,%4};" :: "r"(a), "r"(x), "r"(y), "r"(z), "r"(w));
}
__device__ __forceinline__ void cpasync16(unsigned smem, const void* g) {
    asm volatile("cp.async.cg.shared.global [%0], [%1], 16;" :: "r"(smem), "l"(g));
}
__device__ __forceinline__ void cpcommit() { asm volatile("cp.async.commit_group;"); }
__device__ __forceinline__ void cpwait0() { asm volatile("cp.async.wait_group 0;"); }
__device__ __forceinline__ void ldsm4(unsigned& r0, unsigned& r1, unsigned& r2, unsigned& r3, unsigned a) {
    asm volatile("ldmatrix.sync.aligned.m8n8.x4.shared.b16 {%0,%1,%2,%3}, [%4];"
                 : "=r"(r0), "=r"(r1), "=r"(r2), "=r"(r3) : "r"(a));
}
__device__ __forceinline__ void mma16816(float* c, const unsigned* a, unsigned b0, unsigned b1) {
    asm volatile(
        "mma.sync.aligned.m16n8k16.row.col.f32.f16.f16.f32 "
        "{%0,%1,%2,%3}, {%4,%5,%6,%7}, {%8,%9}, {%0,%1,%2,%3};"
        : "+f"(c[0]), "+f"(c[1]), "+f"(c[2]), "+f"(c[3])
        : "r"(a[0]), "r"(a[1]), "r"(a[2]), "r"(a[3]), "r"(b0), "r"(b1));
}

// smem layout: rows padded to 80B (gcd(80,128)=16 -> conflict-free ldmatrix)
#define ASTR 80
#define SM_A 10240             // 128 rows * 80B
#define SM_B 20480             // 256 rows * 80B
#define SM_STG (SM_A + SM_B)        // one stage: A|B = 30720
#define SM_TOT (2*SM_STG)           // double buffered = 61440

// ---------------- fused layer GEMM (mma.sync fp16, fp16 A path) ----------------
// out[r, m] = relu?( sum_k A[r,k] * W[m,k] + b[m] ), A = [mean_agg | xin] (K=512)
__global__ __launch_bounds__(512) void gemm_mma_kernel(
    int xsel, float* __restrict__ oext, int osel,
    const float* __restrict__ bias, int do_relu)
{
    extern __shared__ char smem[];
    const __half* xin = (xsel == 0) ? g_x0h : ((xsel == 1) ? g_x1h : g_x2h);
    __half* outh = (osel == 1) ? g_x1h : g_x2h;

    const unsigned su = sm_u32(smem);

    const int tid = threadIdx.x;
    const int wid = tid >> 5;
    const int lane = tid & 31;
    const int wm = wid & 1;
    const int wn = wid >> 1;
    const int row0 = blockIdx.x * 128;

    // A loader geometry: 4 threads per row, 8 halfs (16B) each
    const int arow = tid >> 2;
    const int akq = tid & 3;
    const int gr = row0 + arow;
    const bool rok = gr < NN;
    const __half* aggrow = g_acch + (size_t)(rok ? gr : 0) * DD;
    const __half* xrow = xin + (size_t)(rok ? gr : 0) * DD;

    // B loader geometry (cp.async)
    const int brow = tid >> 1;
    const int bkh = (tid & 1) * 16;

    // ldmatrix fragment addresses (stage-relative)
    const unsigned aoff = (unsigned)((wm * 64 + (lane & 15)) * ASTR + (lane >> 4) * 16);
    const unsigned boff = (unsigned)((wn * 32 + ((lane >> 4) & 1) * 8 + (lane & 7)) * ASTR
                                     + ((lane >> 3) & 1) * 16);

    float acc[4][4][4];
    #pragma unroll
    for (int i = 0; i < 4; i++)
        #pragma unroll
        for (int j = 0; j < 4; j++)
            #pragma unroll
            for (int q = 0; q < 4; q++) acc[i][j][q] = 0.f;

    uint4 pa;   // prefetched A chunk (8 fp16)

    auto ldA = [&](int ck) {
        const int side = ck >> 3;
        const __half* s = (side ? xrow : aggrow) + (ck & 7) * 32 + akq * 8;
        if (rok) pa = *(const uint4*)s;
        else pa = make_uint4(0u, 0u, 0u, 0u);
    };
    auto stsA = [&](int stg) {
        unsigned base = su + (unsigned)stg * SM_STG;
        unsigned off = (unsigned)(arow * ASTR + akq * 16);
        sts128(base + off, pa.x, pa.y, pa.z, pa.w);
    };
    auto cpB = [&](int ck, int stg) {
        unsigned base = su + (unsigned)stg * SM_STG + SM_A;
        unsigned off = (unsigned)(brow * ASTR + bkh * 2);
        size_t go = (size_t)brow * 512 + ck * 32 + bkh;
        cpasync16(base + off, g_bh + go);
        cpasync16(base + off + 16, g_bh + go + 8);
        cpcommit();
    };

    // prologue
    ldA(0);
    stsA(0);
    cpB(0, 0);
    ldA(1);

    #pragma unroll 1
    for (int ck = 0; ck < 16; ck++) {
        const int s = ck & 1;
        cpwait0();
        __syncthreads();

        if (ck < 15) {
            stsA(s ^ 1);
            cpB(ck + 1, s ^ 1);
        }
        if (ck < 14) ldA(ck + 2);

        const unsigned sbase = su + (unsigned)s * SM_STG;
        const unsigned suA = sbase;
        const unsigned suB = sbase + SM_A;

        #pragma unroll
        for (int ks = 0; ks < 2; ks++) {
            const unsigned kb = (unsigned)(ks * 32);
            unsigned bh[4][2];
            #pragma unroll
            for (int p = 0; p < 2; p++) {
                ldsm4(bh[2 * p][0], bh[2 * p][1], bh[2 * p + 1][0], bh[2 * p + 1][1],
                      suB + boff + p * (16 * ASTR) + kb);
            }
            #pragma unroll
            for (int mi = 0; mi < 4; mi++) {
                unsigned af[4];
                ldsm4(af[0], af[1], af[2], af[3], suA + aoff + mi * (16 * ASTR) + kb);
                #pragma unroll
                for (int ni = 0; ni < 4; ni++) mma16816(acc[mi][ni], af, bh[ni][0], bh[ni][1]);
            }
        }
    }

    // ---- epilogue: bias + relu; fp32 for final layer, fp16 for intermediates ----
    const int gr2 = lane >> 2;
    const int gc2 = (lane & 3) * 2;
    #pragma unroll
    for (int mi = 0; mi < 4; mi++) {
        const int rbase = row0 + wm * 64 + mi * 16 + gr2;
        #pragma unroll
        for (int h = 0; h < 2; h++) {
            const int r = rbase + h * 8;
            if (r < NN) {
                #pragma unroll
                for (int ni = 0; ni < 4; ni++) {
                    const int c = wn * 32 + ni * 8 + gc2;
                    float2 bv = *(const float2*)(bias + c);
                    float v0 = acc[mi][ni][h * 2 + 0] + bv.x;
                    float v1 = acc[mi][ni][h * 2 + 1] + bv.y;
                    if (do_relu) { v0 = fmaxf(v0, 0.f); v1 = fmaxf(v1, 0.f); }
                    if (osel == 0) {
                        *(float2*)(oext + (size_t)r * DD + c) = make_float2(v0, v1);
                    } else {
                        *(unsigned*)(outh + (size_t)r * DD + c) = h2u(__floats2half2_rn(v0, v1));
                    }
                }
            }
        }
    }
}

// ---------------- launcher ----------------
extern "C" void kernel_launch(void* const* d_in, const int* in_sizes, int n_in,
                              void* d_out, int out_size) {
    (void)in_sizes; (void)n_in; (void)out_size;
    const void* edge = d_in[0];
    const float* x0 = (const float*)d_in[1];
    const float* Wl[3] = {(const float*)d_in[2], (const float*)d_in[5], (const float*)d_in[8]};
    const float* Wr[3] = {(const float*)d_in[3], (const float*)d_in[6], (const float*)d_in[9]};
    const float* bb[3] = {(const float*)d_in[4], (const float*)d_in[7], (const float*)d_in[10]};
    float* out = (float*)d_out;

    static int smem_set = 0;
    if (!smem_set) {
        cudaFuncSetAttribute(gemm_mma_kernel, cudaFuncAttributeMaxDynamicSharedMemorySize, SM_TOT);
        smem_set = 1;
    }

    const int TB = 256;
    const int ecnt = (EE + TB - 1) / TB;
    const int ncnt = (NN + TB - 1) / TB;
    const int wcnt = (256 * 512 + TB - 1) / TB;
    const int ccnt = (NN * DD / 8 + TB - 1) / TB;
    const int ggrid = (NN + 127) / 128;
    const int agrid = (NN * 32 + TB - 1) / TB;

    detect_kernel<<<1, 32>>>((const unsigned int*)edge);
    convert_kernel<<<ecnt, TB>>>(edge);
    cvt0_kernel<<<ccnt, TB>>>(x0);
    zero_deg_kernel<<<ncnt, TB>>>();
    deg_kernel<<<ecnt, TB>>>();
    invdeg_kernel<<<ncnt, TB>>>();
    scanA_kernel<<<NB, 1024>>>();
    scanB_kernel<<<1, 32>>>();
    scanC_kernel<<<NB, 1024>>>();
    fill_kernel<<<ecnt, TB>>>();

    // layer 1
    convw_kernel<<<wcnt, TB>>>(Wl[0], Wr[0]);
    aggregate_kernel<<<agrid, TB>>>(0);
    gemm_mma_kernel<<<ggrid, 512, SM_TOT>>>(0, nullptr, 1, bb[0], 1);

    // layer 2
    convw_kernel<<<wcnt, TB>>>(Wl[1], Wr[1]);
    aggregate_kernel<<<agrid, TB>>>(1);
    gemm_mma_kernel<<<ggrid, 512, SM_TOT>>>(1, nullptr, 2, bb[1], 1);

    // layer 3
    convw_kernel<<<wcnt, TB>>>(Wl[2], Wr[2]);
    aggregate_kernel<<<agrid, TB>>>(2);
    gemm_mma_kernel<<<ggrid, 512, SM_TOT>>>(2, out, 0, bb[2], 0);
}